// round 3
// baseline (speedup 1.0000x reference)
#include <cuda_runtime.h>
#include <cstdint>

#define NH   16
#define DK   64
#define DV   64
#define NB   4
#define NL   512
#define DM   1024
#define BL   (NB*NL)   // 2048

// ---------------- scratch (device globals: allocation-free) ----------------
__device__ float g_qh[NB*NH*NL*DK];   // [b,h,l,dk], pre-scaled by 1/8
__device__ float g_kh[NB*NH*NL*DK];   // [b,h,l,dk]
__device__ float g_vt[NB*NH*DV*NL];   // [b,h,dv,l]  (transposed V)
__device__ float g_ctx[BL*DM];        // [b*l, h*dv]
__device__ float g_out[BL*DM];        // pre-LN output

// ---------------- helpers ----------------
__device__ __forceinline__ unsigned f2tf(float f) {
    unsigned u;
    asm("cvt.rna.tf32.f32 %0, %1;" : "=r"(u) : "f"(f));
    return u;
}

__device__ __forceinline__ void mma_tf32(float* d, const unsigned* a, const unsigned* b) {
    asm volatile(
        "mma.sync.aligned.m16n8k8.row.col.f32.tf32.tf32.f32 "
        "{%0,%1,%2,%3}, {%4,%5,%6,%7}, {%8,%9}, {%0,%1,%2,%3};\n"
        : "+f"(d[0]), "+f"(d[1]), "+f"(d[2]), "+f"(d[3])
        : "r"(a[0]), "r"(a[1]), "r"(a[2]), "r"(a[3]), "r"(b[0]), "r"(b[1]));
}

__device__ __forceinline__ void cp16(void* dst, const void* src) {
    unsigned d = (unsigned)__cvta_generic_to_shared(dst);
    asm volatile("cp.async.cg.shared.global [%0], [%1], 16;\n" :: "r"(d), "l"(src));
}
#define CP_COMMIT() asm volatile("cp.async.commit_group;\n")
#define CP_WAIT(N)  asm volatile("cp.async.wait_group %0;\n" :: "n"(N))

// ---------------- 128x128-tile GEMM, 4 warps, warp tile 64x64 ----------------
//  mode 0: q proj -> g_qh (scaled 0.125) | 1: k -> g_kh | 2: v -> g_vt (transposed)
//  mode 3: out proj + bias + residual -> g_out
#define AS_STR 36
#define BS_STR 136
#define AS_SZ  (128*AS_STR)
#define BS_SZ  (32*BS_STR)

__device__ __forceinline__ void gemm_body(const float* __restrict__ A,
                                          const float* __restrict__ W,
                                          const float* __restrict__ bias,
                                          const float* __restrict__ resid,
                                          int mode) {
    extern __shared__ float sg[];
    float* Asb[2] = { sg, sg + AS_SZ };
    float* Bsb[2] = { sg + 2*AS_SZ, sg + 2*AS_SZ + BS_SZ };

    int tid  = threadIdx.x;
    int warp = tid >> 5, lane = tid & 31;
    int wm = warp >> 1, wn = warp & 1;     // 2 x 2 warps, warp tile 64x64
    int g  = lane >> 2, tg = lane & 3;
    int m0 = blockIdx.y * 128;
    int n0 = blockIdx.x * 128;

    float acc[4][8][4];
#pragma unroll
    for (int i = 0; i < 4; i++)
#pragma unroll
        for (int j = 0; j < 8; j++)
#pragma unroll
            for (int c = 0; c < 4; c++) acc[i][j][c] = 0.f;

    // tile loader: A 128x32, B 32x128 (128 threads)
    auto load_tiles = [&](int kb, int bufi) {
#pragma unroll
        for (int i = 0; i < 8; i++) {
            int e = tid + i * 128;
            int r = e >> 3, s = (e & 7) * 4;
            cp16(&Asb[bufi][r*AS_STR + s], &A[(size_t)(m0 + r)*DM + kb + s]);
        }
#pragma unroll
        for (int i = 0; i < 8; i++) {
            int e = tid + i * 128;
            int r = e >> 5, s = (e & 31) * 4;
            cp16(&Bsb[bufi][r*BS_STR + s], &W[(size_t)(kb + r)*DM + n0 + s]);
        }
        CP_COMMIT();
    };

    load_tiles(0, 0);
    int buf = 0;
    for (int kb = 0; kb < DM; kb += 32) {
        if (kb + 32 < DM) { load_tiles(kb + 32, buf ^ 1); CP_WAIT(1); }
        else              { CP_WAIT(0); }
        __syncthreads();
        const float* Ab = Asb[buf];
        const float* Bb = Bsb[buf];
#pragma unroll
        for (int ks = 0; ks < 4; ks++) {
            unsigned af[4][4];
#pragma unroll
            for (int mi = 0; mi < 4; mi++) {
                int m = wm * 64 + mi * 16;
                af[mi][0] = f2tf(Ab[(m + g)*AS_STR     + ks*8 + tg]);
                af[mi][1] = f2tf(Ab[(m + g + 8)*AS_STR + ks*8 + tg]);
                af[mi][2] = f2tf(Ab[(m + g)*AS_STR     + ks*8 + tg + 4]);
                af[mi][3] = f2tf(Ab[(m + g + 8)*AS_STR + ks*8 + tg + 4]);
            }
            unsigned bf[8][2];
#pragma unroll
            for (int jj = 0; jj < 8; jj++) {
                int n = wn * 64 + jj * 8;
                bf[jj][0] = f2tf(Bb[(ks*8 + tg)*BS_STR     + n + g]);
                bf[jj][1] = f2tf(Bb[(ks*8 + tg + 4)*BS_STR + n + g]);
            }
#pragma unroll
            for (int mi = 0; mi < 4; mi++)
#pragma unroll
                for (int jj = 0; jj < 8; jj++)
                    mma_tf32(acc[mi][jj], af[mi], bf[jj]);
        }
        __syncthreads();
        buf ^= 1;
    }

#pragma unroll
    for (int mi = 0; mi < 4; mi++) {
#pragma unroll
        for (int j = 0; j < 8; j++) {
#pragma unroll
            for (int c = 0; c < 4; c++) {
                int m  = wm * 64 + mi * 16 + g + ((c >= 2) ? 8 : 0);
                int n  = wn * 64 + j * 8 + 2 * tg + (c & 1);
                int gm = m0 + m;              // b*512 + l
                int gn = n0 + n;              // h*64 + d (modes 0-2)
                float val = acc[mi][j][c] + bias[gn];
                if (mode == 3) {
                    g_out[(size_t)gm * DM + gn] = val + resid[(size_t)gm * DM + gn];
                } else {
                    int b = gm >> 9, l = gm & 511, h = gn >> 6, d = gn & 63;
                    if (mode == 0)
                        g_qh[(((size_t)(b * NH + h) * NL + l)) * DK + d] = val * 0.125f;
                    else if (mode == 1)
                        g_kh[(((size_t)(b * NH + h) * NL + l)) * DK + d] = val;
                    else
                        g_vt[(((size_t)(b * NH + h) * DV + d)) * NL + l] = val;
                }
            }
        }
    }
}

__global__ __launch_bounds__(128, 2) void gemm_qkv_kernel(
    const float* __restrict__ q, const float* __restrict__ k, const float* __restrict__ v,
    const float* __restrict__ wq, const float* __restrict__ bq,
    const float* __restrict__ wk, const float* __restrict__ bk,
    const float* __restrict__ wv, const float* __restrict__ bv) {
    int mode = blockIdx.z;
    const float* X = (mode == 0) ? q  : (mode == 1) ? k  : v;
    const float* W = (mode == 0) ? wq : (mode == 1) ? wk : wv;
    const float* B = (mode == 0) ? bq : (mode == 1) ? bk : bv;
    gemm_body(X, W, B, nullptr, mode);
}

__global__ __launch_bounds__(128, 2) void gemm_out_kernel(
    const float* __restrict__ resid, const float* __restrict__ wo,
    const float* __restrict__ bo) {
    gemm_body(g_ctx, wo, bo, resid, 3);
}

// ---------------- flash attention: 4 warps, 32 q-rows per warp ----------------
#define KV_STR 68
#define KV_SZ  (64*KV_STR)

__global__ __launch_bounds__(128, 2) void attn_kernel(const float* __restrict__ bias,
                                                      const float* __restrict__ gbias) {
    extern __shared__ float sm[];
    float* sKb[2] = { sm, sm + KV_SZ };
    float* sVb[2] = { sm + 2*KV_SZ, sm + 3*KV_SZ };
    unsigned* sP  = (unsigned*)(sm + 4*KV_SZ);   // [128][68]

    int tid = threadIdx.x, wid = tid >> 5, lane = tid & 31;
    int g = lane >> 2, tg = lane & 3;
    int qt = blockIdx.x, h = blockIdx.y, b = blockIdx.z;
    int bh = b * NH + h;
    const float* kbase = g_kh + (size_t)bh * NL * DK;
    const float* vbase = g_vt + (size_t)bh * DV * NL;
    int qrow0 = qt * 128 + wid * 32;             // warp's first query row (within head)
    const float* qptr = g_qh + ((size_t)bh * NL + qrow0) * DK;

    // bias row pointers for the 4 row-groups this thread touches
    const float* brow[4]; const float* grow[4];
#pragma unroll
    for (int rg = 0; rg < 4; rg++) {
        int r = qrow0 + (rg >> 1) * 16 + g + ((rg & 1) ? 8 : 0);
        brow[rg] = bias  + ((size_t)bh * NL + r) * NL;
        grow[rg] = gbias + ((size_t)bh * NL + r) * NL;
    }

    // Q fragments in registers (g_qh pre-scaled by 1/8), 2 m-frags
    unsigned qf[2][8][4];
#pragma unroll
    for (int mi = 0; mi < 2; mi++) {
        const float* qp = qptr + (size_t)mi * 16 * DK;
#pragma unroll
        for (int ks = 0; ks < 8; ks++) {
            qf[mi][ks][0] = f2tf(qp[g * DK       + ks*8 + tg]);
            qf[mi][ks][1] = f2tf(qp[(g + 8) * DK + ks*8 + tg]);
            qf[mi][ks][2] = f2tf(qp[g * DK       + ks*8 + tg + 4]);
            qf[mi][ks][3] = f2tf(qp[(g + 8) * DK + ks*8 + tg + 4]);
        }
    }

    float oacc[2][8][4];
#pragma unroll
    for (int mi = 0; mi < 2; mi++)
#pragma unroll
        for (int j = 0; j < 8; j++)
#pragma unroll
            for (int c = 0; c < 4; c++) oacc[mi][j][c] = 0.f;
    float mrow[4] = {-1e30f, -1e30f, -1e30f, -1e30f};
    float lrow[4] = {0.f, 0.f, 0.f, 0.f};

    // P staging pointers (fixed rows per thread)
    unsigned* prow[4];
#pragma unroll
    for (int rg = 0; rg < 4; rg++)
        prow[rg] = sP + (wid*32 + (rg >> 1)*16 + g + ((rg & 1) ? 8 : 0)) * KV_STR;

    auto load_kv = [&](int kt, int bufi) {
#pragma unroll
        for (int i = 0; i < 8; i++) {
            int e = tid + i * 128;
            int r = e >> 4, s = (e & 15) * 4;
            cp16(&sKb[bufi][r*KV_STR + s], &kbase[(size_t)(kt*64 + r) * DK + s]);
        }
#pragma unroll
        for (int i = 0; i < 8; i++) {
            int e = tid + i * 128;
            int r = e >> 4, s = (e & 15) * 4;
            cp16(&sVb[bufi][r*KV_STR + s], &vbase[(size_t)r * NL + kt*64 + s]);
        }
        CP_COMMIT();
    };

    load_kv(0, 0);
    for (int kt = 0; kt < 8; kt++) {
        int cur = kt & 1;
        if (kt < 7) { load_kv(kt + 1, cur ^ 1); CP_WAIT(1); }
        else        { CP_WAIT(0); }
        __syncthreads();

        // S accumulators initialized with both biases
        float sacc[2][8][4];
#pragma unroll
        for (int j = 0; j < 8; j++) {
            int col = kt * 64 + j * 8 + 2 * tg;
#pragma unroll
            for (int rg = 0; rg < 4; rg++) {
                float2 bb = *(const float2*)(brow[rg] + col);
                float2 gg = *(const float2*)(grow[rg] + col);
                sacc[rg >> 1][j][(rg & 1) ? 2 : 0] = bb.x + gg.x;
                sacc[rg >> 1][j][(rg & 1) ? 3 : 1] = bb.y + gg.y;
            }
        }

        const float* Kb = sKb[cur];
#pragma unroll
        for (int ks = 0; ks < 8; ks++) {
            unsigned bf[8][2];
#pragma unroll
            for (int jj = 0; jj < 8; jj++) {
                int n = jj * 8;
                bf[jj][0] = f2tf(Kb[(n + g)*KV_STR + ks*8 + tg]);
                bf[jj][1] = f2tf(Kb[(n + g)*KV_STR + ks*8 + tg + 4]);
            }
#pragma unroll
            for (int mi = 0; mi < 2; mi++)
#pragma unroll
                for (int jj = 0; jj < 8; jj++)
                    mma_tf32(sacc[mi][jj], qf[mi][ks], bf[jj]);
        }

        // ---- online softmax (4 warp-private row-groups; quad owns a row) ----
        float tmax[4] = {-1e30f, -1e30f, -1e30f, -1e30f};
#pragma unroll
        for (int j = 0; j < 8; j++) {
            tmax[0] = fmaxf(tmax[0], fmaxf(sacc[0][j][0], sacc[0][j][1]));
            tmax[1] = fmaxf(tmax[1], fmaxf(sacc[0][j][2], sacc[0][j][3]));
            tmax[2] = fmaxf(tmax[2], fmaxf(sacc[1][j][0], sacc[1][j][1]));
            tmax[3] = fmaxf(tmax[3], fmaxf(sacc[1][j][2], sacc[1][j][3]));
        }
        float rsc[4], ssum[4];
#pragma unroll
        for (int rg = 0; rg < 4; rg++) {
            tmax[rg] = fmaxf(tmax[rg], __shfl_xor_sync(~0u, tmax[rg], 1));
            tmax[rg] = fmaxf(tmax[rg], __shfl_xor_sync(~0u, tmax[rg], 2));
            float mn = fmaxf(mrow[rg], tmax[rg]);
            rsc[rg] = __expf(mrow[rg] - mn);
            mrow[rg] = mn;
            ssum[rg] = 0.f;
        }
#pragma unroll
        for (int j = 0; j < 8; j++) {
            sacc[0][j][0] = __expf(sacc[0][j][0] - mrow[0]); ssum[0] += sacc[0][j][0];
            sacc[0][j][1] = __expf(sacc[0][j][1] - mrow[0]); ssum[0] += sacc[0][j][1];
            sacc[0][j][2] = __expf(sacc[0][j][2] - mrow[1]); ssum[1] += sacc[0][j][2];
            sacc[0][j][3] = __expf(sacc[0][j][3] - mrow[1]); ssum[1] += sacc[0][j][3];
            sacc[1][j][0] = __expf(sacc[1][j][0] - mrow[2]); ssum[2] += sacc[1][j][0];
            sacc[1][j][1] = __expf(sacc[1][j][1] - mrow[2]); ssum[2] += sacc[1][j][1];
            sacc[1][j][2] = __expf(sacc[1][j][2] - mrow[3]); ssum[3] += sacc[1][j][2];
            sacc[1][j][3] = __expf(sacc[1][j][3] - mrow[3]); ssum[3] += sacc[1][j][3];
        }
#pragma unroll
        for (int rg = 0; rg < 4; rg++) {
            ssum[rg] += __shfl_xor_sync(~0u, ssum[rg], 1);
            ssum[rg] += __shfl_xor_sync(~0u, ssum[rg], 2);
            lrow[rg] = lrow[rg] * rsc[rg] + ssum[rg];
        }
#pragma unroll
        for (int mi = 0; mi < 2; mi++)
#pragma unroll
            for (int j = 0; j < 8; j++) {
                oacc[mi][j][0] *= rsc[mi*2];     oacc[mi][j][1] *= rsc[mi*2];
                oacc[mi][j][2] *= rsc[mi*2 + 1]; oacc[mi][j][3] *= rsc[mi*2 + 1];
            }

        // ---- P -> smem (warp-private rows), then PV mma ----
#pragma unroll
        for (int j = 0; j < 8; j++) {
            int n = j * 8 + 2 * tg;
            prow[0][n]     = f2tf(sacc[0][j][0]);
            prow[0][n + 1] = f2tf(sacc[0][j][1]);
            prow[1][n]     = f2tf(sacc[0][j][2]);
            prow[1][n + 1] = f2tf(sacc[0][j][3]);
            prow[2][n]     = f2tf(sacc[1][j][0]);
            prow[2][n + 1] = f2tf(sacc[1][j][1]);
            prow[3][n]     = f2tf(sacc[1][j][2]);
            prow[3][n + 1] = f2tf(sacc[1][j][3]);
        }
        __syncwarp();

        const float* Vb = sVb[cur];
#pragma unroll
        for (int ks = 0; ks < 8; ks++) {
            int kk = ks * 8;
            unsigned af[2][4];
#pragma unroll
            for (int mi = 0; mi < 2; mi++) {
                af[mi][0] = prow[mi*2][kk + tg];
                af[mi][1] = prow[mi*2 + 1][kk + tg];
                af[mi][2] = prow[mi*2][kk + tg + 4];
                af[mi][3] = prow[mi*2 + 1][kk + tg + 4];
            }
            unsigned bf[8][2];
#pragma unroll
            for (int jj = 0; jj < 8; jj++) {
                int n = jj * 8;       // dv
                bf[jj][0] = f2tf(Vb[(n + g)*KV_STR + kk + tg]);
                bf[jj][1] = f2tf(Vb[(n + g)*KV_STR + kk + tg + 4]);
            }
#pragma unroll
            for (int mi = 0; mi < 2; mi++)
#pragma unroll
                for (int jj = 0; jj < 8; jj++)
                    mma_tf32(oacc[mi][jj], af[mi], bf[jj]);
        }
        __syncthreads();
    }

    // epilogue: normalize and write ctx
    float inv[4];
#pragma unroll
    for (int rg = 0; rg < 4; rg++) inv[rg] = 1.f / lrow[rg];
#pragma unroll
    for (int mi = 0; mi < 2; mi++) {
        size_t gr0 = (size_t)b * NL + qt * 128 + wid * 32 + mi * 16 + g;
        float* out0 = g_ctx + gr0 * DM + h * DV;
        float* out1 = out0 + (size_t)8 * DM;
#pragma unroll
        for (int j = 0; j < 8; j++) {
            int n = j * 8 + 2 * tg;
            *(float2*)(out0 + n) = make_float2(oacc[mi][j][0] * inv[mi*2],
                                               oacc[mi][j][1] * inv[mi*2]);
            *(float2*)(out1 + n) = make_float2(oacc[mi][j][2] * inv[mi*2+1],
                                               oacc[mi][j][3] * inv[mi*2+1]);
        }
    }
}

// ---------------- LayerNorm ----------------
__global__ __launch_bounds__(256) void ln_kernel(const float* __restrict__ gamma,
                                                 const float* __restrict__ beta,
                                                 float* __restrict__ out) {
    __shared__ float red[16];
    int row = blockIdx.x, tid = threadIdx.x;
    const float* x = g_out + (size_t)row * DM;
    float v[4];
    float s = 0.f, s2 = 0.f;
#pragma unroll
    for (int i = 0; i < 4; i++) {
        v[i] = x[tid + i * 256];
        s += v[i]; s2 += v[i] * v[i];
    }
#pragma unroll
    for (int o = 16; o; o >>= 1) {
        s  += __shfl_xor_sync(~0u, s, o);
        s2 += __shfl_xor_sync(~0u, s2, o);
    }
    int warp = tid >> 5, lane = tid & 31;
    if (lane == 0) { red[warp] = s; red[warp + 8] = s2; }
    __syncthreads();
    float ts = 0.f, ts2 = 0.f;
#pragma unroll
    for (int i = 0; i < 8; i++) { ts += red[i]; ts2 += red[i + 8]; }
    float mean = ts * (1.f / DM);
    float var  = ts2 * (1.f / DM) - mean * mean;
    float inv  = rsqrtf(var + 1e-6f);
#pragma unroll
    for (int i = 0; i < 4; i++) {
        int d = tid + i * 256;
        out[(size_t)row * DM + d] = (v[i] - mean) * inv * gamma[d] + beta[d];
    }
}

// ---------------- launch ----------------
extern "C" void kernel_launch(void* const* d_in, const int* in_sizes, int n_in,
                              void* d_out, int out_size) {
    const float* q     = (const float*)d_in[0];
    const float* k     = (const float*)d_in[1];
    const float* v     = (const float*)d_in[2];
    const float* bias  = (const float*)d_in[3];
    const float* gbias = (const float*)d_in[4];
    const float* wq    = (const float*)d_in[5];
    const float* bq    = (const float*)d_in[6];
    const float* wk    = (const float*)d_in[7];
    const float* bk    = (const float*)d_in[8];
    const float* wv    = (const float*)d_in[9];
    const float* bv    = (const float*)d_in[10];
    const float* wo    = (const float*)d_in[11];
    const float* bo    = (const float*)d_in[12];
    const float* ln_g  = (const float*)d_in[13];
    const float* ln_b  = (const float*)d_in[14];
    float* out = (float*)d_out;

    const int gemm_smem = (2*AS_SZ + 2*BS_SZ) * (int)sizeof(float);        // 71,680 B
    const int attn_smem = (4*KV_SZ + 128*KV_STR) * (int)sizeof(float);     // 104,448 B
    cudaFuncSetAttribute((const void*)gemm_qkv_kernel,
                         cudaFuncAttributeMaxDynamicSharedMemorySize, gemm_smem);
    cudaFuncSetAttribute((const void*)gemm_out_kernel,
                         cudaFuncAttributeMaxDynamicSharedMemorySize, gemm_smem);
    cudaFuncSetAttribute((const void*)attn_kernel,
                         cudaFuncAttributeMaxDynamicSharedMemorySize, attn_smem);

    gemm_qkv_kernel<<<dim3(8, 16, 3), 128, gemm_smem>>>(q, k, v, wq, bq, wk, bk, wv, bv);
    attn_kernel<<<dim3(4, NH, NB), 128, attn_smem>>>(bias, gbias);
    gemm_out_kernel<<<dim3(8, 16), 128, gemm_smem>>>(q, wo, bo);
    ln_kernel<<<BL, 256>>>(ln_g, ln_b, out);
}

// round 4
// speedup vs baseline: 1.1746x; 1.1746x over previous
#include <cuda_runtime.h>
#include <cstdint>

#define NH   16
#define DK   64
#define DV   64
#define NB   4
#define NL   512
#define DM   1024
#define BL   (NB*NL)   // 2048

// ---------------- scratch (device globals: allocation-free) ----------------
__device__ float g_qh[NB*NH*NL*DK];   // [b,h,l,dk], pre-scaled by 1/8
__device__ float g_kh[NB*NH*NL*DK];   // [b,h,l,dk]
__device__ float g_vt[NB*NH*DV*NL];   // [b,h,dv,l]  (transposed V)
__device__ float g_ctx[BL*DM];        // [b*l, h*dv]
__device__ float g_out[BL*DM];        // pre-LN output

// ---------------- helpers ----------------
// tf32 mma fed with RAW fp32 bits (HW uses bits[31:13]; truncation vs RNA
// costs ~1 ulp_tf32 -> rel_err ~2e-4, well under 1e-3)
__device__ __forceinline__ void mma_tf32(float* d, const unsigned* a, const unsigned* b) {
    asm volatile(
        "mma.sync.aligned.m16n8k8.row.col.f32.tf32.tf32.f32 "
        "{%0,%1,%2,%3}, {%4,%5,%6,%7}, {%8,%9}, {%0,%1,%2,%3};\n"
        : "+f"(d[0]), "+f"(d[1]), "+f"(d[2]), "+f"(d[3])
        : "r"(a[0]), "r"(a[1]), "r"(a[2]), "r"(a[3]), "r"(b[0]), "r"(b[1]));
}

__device__ __forceinline__ void cp16(void* dst, const void* src) {
    unsigned d = (unsigned)__cvta_generic_to_shared(dst);
    asm volatile("cp.async.cg.shared.global [%0], [%1], 16;\n" :: "r"(d), "l"(src));
}
#define CP_COMMIT() asm volatile("cp.async.commit_group;\n")
#define CP_WAIT(N)  asm volatile("cp.async.wait_group %0;\n" :: "n"(N))

// ---------------- 128x128-tile GEMM (256 thr, 8 warps, warp tile 32x64) -----
//  mode 0: q proj -> g_qh (scaled 0.125) | 1: k -> g_kh | 2: v -> g_vt (transposed)
//  mode 3: out proj + bias + residual -> g_out
#define AS_STR 36
#define BS_STR 136
#define AS_SZ  (128*AS_STR)
#define BS_SZ  (32*BS_STR)

__device__ __forceinline__ void gemm_body(const float* __restrict__ A,
                                          const float* __restrict__ W,
                                          const float* __restrict__ bias,
                                          const float* __restrict__ resid,
                                          int mode) {
    extern __shared__ float sg[];
    float* Asb[2] = { sg, sg + AS_SZ };
    float* Bsb[2] = { sg + 2*AS_SZ, sg + 2*AS_SZ + BS_SZ };

    int tid  = threadIdx.x;
    int warp = tid >> 5, lane = tid & 31;
    int wm = warp >> 1, wn = warp & 1;     // 4 x 2 warps over 128x128
    int g  = lane >> 2, tg = lane & 3;
    int m0 = blockIdx.y * 128;
    int n0 = blockIdx.x * 128;

    float acc[2][8][4];
#pragma unroll
    for (int i = 0; i < 2; i++)
#pragma unroll
        for (int j = 0; j < 8; j++)
#pragma unroll
            for (int c = 0; c < 4; c++) acc[i][j][c] = 0.f;

    auto load_tiles = [&](int kb, int bufi) {
#pragma unroll
        for (int i = 0; i < 4; i++) {
            int e = tid + i * 256;
            int r = e >> 3, s = (e & 7) * 4;
            cp16(&Asb[bufi][r*AS_STR + s], &A[(size_t)(m0 + r)*DM + kb + s]);
        }
#pragma unroll
        for (int i = 0; i < 4; i++) {
            int e = tid + i * 256;
            int r = e >> 5, s = (e & 31) * 4;
            cp16(&Bsb[bufi][r*BS_STR + s], &W[(size_t)(kb + r)*DM + n0 + s]);
        }
        CP_COMMIT();
    };

    load_tiles(0, 0);
    int buf = 0;
    for (int kb = 0; kb < DM; kb += 32) {
        if (kb + 32 < DM) { load_tiles(kb + 32, buf ^ 1); CP_WAIT(1); }
        else              { CP_WAIT(0); }
        __syncthreads();
        const unsigned* Ab = (const unsigned*)Asb[buf];
        const unsigned* Bb = (const unsigned*)Bsb[buf];
#pragma unroll
        for (int ks = 0; ks < 4; ks++) {
            unsigned af[2][4];
#pragma unroll
            for (int i = 0; i < 2; i++) {
                int m = wm * 32 + i * 16;
                af[i][0] = Ab[(m + g)*AS_STR     + ks*8 + tg];
                af[i][1] = Ab[(m + g + 8)*AS_STR + ks*8 + tg];
                af[i][2] = Ab[(m + g)*AS_STR     + ks*8 + tg + 4];
                af[i][3] = Ab[(m + g + 8)*AS_STR + ks*8 + tg + 4];
            }
#pragma unroll
            for (int jh = 0; jh < 2; jh++) {
                unsigned bf[4][2];
#pragma unroll
                for (int jj = 0; jj < 4; jj++) {
                    int n = wn * 64 + (jh*4 + jj) * 8;
                    bf[jj][0] = Bb[(ks*8 + tg)*BS_STR     + n + g];
                    bf[jj][1] = Bb[(ks*8 + tg + 4)*BS_STR + n + g];
                }
#pragma unroll
                for (int i = 0; i < 2; i++)
#pragma unroll
                    for (int jj = 0; jj < 4; jj++)
                        mma_tf32(acc[i][jh*4 + jj], af[i], bf[jj]);
            }
        }
        __syncthreads();
        buf ^= 1;
    }

#pragma unroll
    for (int i = 0; i < 2; i++) {
#pragma unroll
        for (int j = 0; j < 8; j++) {
#pragma unroll
            for (int c = 0; c < 4; c++) {
                int m  = wm * 32 + i * 16 + g + ((c >= 2) ? 8 : 0);
                int n  = wn * 64 + j * 8 + 2 * tg + (c & 1);
                int gm = m0 + m;              // b*512 + l
                int gn = n0 + n;              // h*64 + d (modes 0-2)
                float val = acc[i][j][c] + bias[gn];
                if (mode == 3) {
                    g_out[(size_t)gm * DM + gn] = val + resid[(size_t)gm * DM + gn];
                } else {
                    int b = gm >> 9, l = gm & 511, h = gn >> 6, d = gn & 63;
                    if (mode == 0)
                        g_qh[(((size_t)(b * NH + h) * NL + l)) * DK + d] = val * 0.125f;
                    else if (mode == 1)
                        g_kh[(((size_t)(b * NH + h) * NL + l)) * DK + d] = val;
                    else
                        g_vt[(((size_t)(b * NH + h) * DV + d)) * NL + l] = val;
                }
            }
        }
    }
}

__global__ __launch_bounds__(256, 2) void gemm_qkv_kernel(
    const float* __restrict__ q, const float* __restrict__ k, const float* __restrict__ v,
    const float* __restrict__ wq, const float* __restrict__ bq,
    const float* __restrict__ wk, const float* __restrict__ bk,
    const float* __restrict__ wv, const float* __restrict__ bv) {
    int mode = blockIdx.z;
    const float* X = (mode == 0) ? q  : (mode == 1) ? k  : v;
    const float* W = (mode == 0) ? wq : (mode == 1) ? wk : wv;
    const float* B = (mode == 0) ? bq : (mode == 1) ? bk : bv;
    gemm_body(X, W, B, nullptr, mode);
}

__global__ __launch_bounds__(256, 2) void gemm_out_kernel(
    const float* __restrict__ resid, const float* __restrict__ wo,
    const float* __restrict__ bo) {
    gemm_body(g_ctx, wo, bo, resid, 3);
}

// ---------------- flash attention (256 thr, 8 warps x 16 q-rows) ------------
#define KV_STR 68
#define KV_SZ  (64*KV_STR)

__global__ __launch_bounds__(256, 2) void attn_kernel(const float* __restrict__ bias,
                                                      const float* __restrict__ gbias) {
    extern __shared__ float sm[];
    float* sKb[2] = { sm, sm + KV_SZ };
    float* sVb[2] = { sm + 2*KV_SZ, sm + 3*KV_SZ };
    unsigned* sP  = (unsigned*)(sm + 4*KV_SZ);   // [128][68]

    int tid = threadIdx.x, wid = tid >> 5, lane = tid & 31;
    int g = lane >> 2, tg = lane & 3;
    int qt = blockIdx.x, h = blockIdx.y, b = blockIdx.z;
    int bh = b * NH + h;
    const float* kbase = g_kh + (size_t)bh * NL * DK;
    const float* vbase = g_vt + (size_t)bh * DV * NL;
    int qrow0 = qt * 128 + wid * 16;
    const float* qptr = g_qh + ((size_t)bh * NL + qrow0) * DK;
    const float* brow0 = bias  + ((size_t)bh * NL + qrow0 + g) * NL;
    const float* brow1 = brow0 + 8 * NL;
    const float* grow0 = gbias + ((size_t)bh * NL + qrow0 + g) * NL;
    const float* grow1 = grow0 + 8 * NL;

    // Q fragments (raw fp32 bits; g_qh pre-scaled by 1/8)
    unsigned qf[8][4];
#pragma unroll
    for (int ks = 0; ks < 8; ks++) {
        qf[ks][0] = __float_as_uint(qptr[g * DK       + ks*8 + tg]);
        qf[ks][1] = __float_as_uint(qptr[(g + 8) * DK + ks*8 + tg]);
        qf[ks][2] = __float_as_uint(qptr[g * DK       + ks*8 + tg + 4]);
        qf[ks][3] = __float_as_uint(qptr[(g + 8) * DK + ks*8 + tg + 4]);
    }

    float oacc[8][4];
#pragma unroll
    for (int j = 0; j < 8; j++)
#pragma unroll
        for (int c = 0; c < 4; c++) oacc[j][c] = 0.f;
    float m0 = -1e30f, m1 = -1e30f, l0 = 0.f, l1 = 0.f;

    auto load_kv = [&](int kt, int bufi) {
#pragma unroll
        for (int i = 0; i < 4; i++) {
            int e = tid + i * 256;
            int r = e >> 4, s = (e & 15) * 4;
            cp16(&sKb[bufi][r*KV_STR + s], &kbase[(size_t)(kt*64 + r) * DK + s]);
        }
#pragma unroll
        for (int i = 0; i < 4; i++) {
            int e = tid + i * 256;
            int r = e >> 4, s = (e & 15) * 4;
            cp16(&sVb[bufi][r*KV_STR + s], &vbase[(size_t)r * NL + kt*64 + s]);
        }
        CP_COMMIT();
    };

    load_kv(0, 0);
    for (int kt = 0; kt < 8; kt++) {
        int cur = kt & 1;
        if (kt < 7) { load_kv(kt + 1, cur ^ 1); CP_WAIT(1); }
        else        { CP_WAIT(0); }
        __syncthreads();

        // S accumulator initialized with both biases
        float sacc[8][4];
#pragma unroll
        for (int j = 0; j < 8; j++) {
            int col = kt * 64 + j * 8 + 2 * tg;
            float2 b0  = *(const float2*)(brow0 + col);
            float2 gb0 = *(const float2*)(grow0 + col);
            float2 b1  = *(const float2*)(brow1 + col);
            float2 gb1 = *(const float2*)(grow1 + col);
            sacc[j][0] = b0.x + gb0.x; sacc[j][1] = b0.y + gb0.y;
            sacc[j][2] = b1.x + gb1.x; sacc[j][3] = b1.y + gb1.y;
        }

        const unsigned* Kb = (const unsigned*)sKb[cur];
#pragma unroll
        for (int ks = 0; ks < 8; ks++) {
#pragma unroll
            for (int jh = 0; jh < 2; jh++) {
                unsigned bf[4][2];
#pragma unroll
                for (int jj = 0; jj < 4; jj++) {
                    int n = (jh*4 + jj) * 8;
                    bf[jj][0] = Kb[(n + g)*KV_STR + ks*8 + tg];
                    bf[jj][1] = Kb[(n + g)*KV_STR + ks*8 + tg + 4];
                }
#pragma unroll
                for (int jj = 0; jj < 4; jj++) mma_tf32(sacc[jh*4 + jj], qf[ks], bf[jj]);
            }
        }

        // ---- online softmax (warp-private rows; quad owns a row) ----
        float t0 = -1e30f, t1 = -1e30f;
#pragma unroll
        for (int j = 0; j < 8; j++) {
            t0 = fmaxf(t0, fmaxf(sacc[j][0], sacc[j][1]));
            t1 = fmaxf(t1, fmaxf(sacc[j][2], sacc[j][3]));
        }
        t0 = fmaxf(t0, __shfl_xor_sync(~0u, t0, 1));
        t0 = fmaxf(t0, __shfl_xor_sync(~0u, t0, 2));
        t1 = fmaxf(t1, __shfl_xor_sync(~0u, t1, 1));
        t1 = fmaxf(t1, __shfl_xor_sync(~0u, t1, 2));
        float mn0 = fmaxf(m0, t0), mn1 = fmaxf(m1, t1);
        float r0 = __expf(m0 - mn0), r1 = __expf(m1 - mn1);
        float s0 = 0.f, s1 = 0.f;
#pragma unroll
        for (int j = 0; j < 8; j++) {
            sacc[j][0] = __expf(sacc[j][0] - mn0); s0 += sacc[j][0];
            sacc[j][1] = __expf(sacc[j][1] - mn0); s0 += sacc[j][1];
            sacc[j][2] = __expf(sacc[j][2] - mn1); s1 += sacc[j][2];
            sacc[j][3] = __expf(sacc[j][3] - mn1); s1 += sacc[j][3];
        }
        s0 += __shfl_xor_sync(~0u, s0, 1); s0 += __shfl_xor_sync(~0u, s0, 2);
        s1 += __shfl_xor_sync(~0u, s1, 1); s1 += __shfl_xor_sync(~0u, s1, 2);
        l0 = l0 * r0 + s0; l1 = l1 * r1 + s1;
        m0 = mn0; m1 = mn1;
#pragma unroll
        for (int j = 0; j < 8; j++) {
            oacc[j][0] *= r0; oacc[j][1] *= r0;
            oacc[j][2] *= r1; oacc[j][3] *= r1;
        }

        // ---- P -> smem (raw bits, warp-private rows), then PV mma ----
        unsigned* p0 = sP + (wid*16 + g) * KV_STR;
        unsigned* p1 = sP + (wid*16 + g + 8) * KV_STR;
#pragma unroll
        for (int j = 0; j < 8; j++) {
            int n = j * 8 + 2 * tg;
            p0[n]     = __float_as_uint(sacc[j][0]);
            p0[n + 1] = __float_as_uint(sacc[j][1]);
            p1[n]     = __float_as_uint(sacc[j][2]);
            p1[n + 1] = __float_as_uint(sacc[j][3]);
        }
        __syncwarp();

        const unsigned* Vb = (const unsigned*)sVb[cur];
#pragma unroll
        for (int ks = 0; ks < 8; ks++) {
            unsigned af[4];
            af[0] = p0[ks*8 + tg];
            af[1] = p1[ks*8 + tg];
            af[2] = p0[ks*8 + tg + 4];
            af[3] = p1[ks*8 + tg + 4];
#pragma unroll
            for (int jh = 0; jh < 2; jh++) {
                unsigned bf[4][2];
#pragma unroll
                for (int jj = 0; jj < 4; jj++) {
                    int n = (jh*4 + jj) * 8;       // dv
                    bf[jj][0] = Vb[(n + g)*KV_STR + ks*8 + tg];
                    bf[jj][1] = Vb[(n + g)*KV_STR + ks*8 + tg + 4];
                }
#pragma unroll
                for (int jj = 0; jj < 4; jj++) mma_tf32(oacc[jh*4 + jj], af, bf[jj]);
            }
        }
        __syncthreads();
    }

    // epilogue: normalize and write ctx
    float inv0 = 1.f / l0, inv1 = 1.f / l1;
    size_t gr0 = (size_t)b * NL + qt * 128 + wid * 16 + g;
    float* out0 = g_ctx + gr0 * DM + h * DV;
    float* out1 = out0 + (size_t)8 * DM;
#pragma unroll
    for (int j = 0; j < 8; j++) {
        int n = j * 8 + 2 * tg;
        *(float2*)(out0 + n) = make_float2(oacc[j][0] * inv0, oacc[j][1] * inv0);
        *(float2*)(out1 + n) = make_float2(oacc[j][2] * inv1, oacc[j][3] * inv1);
    }
}

// ---------------- LayerNorm ----------------
__global__ __launch_bounds__(256) void ln_kernel(const float* __restrict__ gamma,
                                                 const float* __restrict__ beta,
                                                 float* __restrict__ out) {
    __shared__ float red[16];
    int row = blockIdx.x, tid = threadIdx.x;
    const float* x = g_out + (size_t)row * DM;
    float v[4];
    float s = 0.f, s2 = 0.f;
#pragma unroll
    for (int i = 0; i < 4; i++) {
        v[i] = x[tid + i * 256];
        s += v[i]; s2 += v[i] * v[i];
    }
#pragma unroll
    for (int o = 16; o; o >>= 1) {
        s  += __shfl_xor_sync(~0u, s, o);
        s2 += __shfl_xor_sync(~0u, s2, o);
    }
    int warp = tid >> 5, lane = tid & 31;
    if (lane == 0) { red[warp] = s; red[warp + 8] = s2; }
    __syncthreads();
    float ts = 0.f, ts2 = 0.f;
#pragma unroll
    for (int i = 0; i < 8; i++) { ts += red[i]; ts2 += red[i + 8]; }
    float mean = ts * (1.f / DM);
    float var  = ts2 * (1.f / DM) - mean * mean;
    float inv  = rsqrtf(var + 1e-6f);
#pragma unroll
    for (int i = 0; i < 4; i++) {
        int d = tid + i * 256;
        out[(size_t)row * DM + d] = (v[i] - mean) * inv * gamma[d] + beta[d];
    }
}

// ---------------- launch ----------------
extern "C" void kernel_launch(void* const* d_in, const int* in_sizes, int n_in,
                              void* d_out, int out_size) {
    const float* q     = (const float*)d_in[0];
    const float* k     = (const float*)d_in[1];
    const float* v     = (const float*)d_in[2];
    const float* bias  = (const float*)d_in[3];
    const float* gbias = (const float*)d_in[4];
    const float* wq    = (const float*)d_in[5];
    const float* bq    = (const float*)d_in[6];
    const float* wk    = (const float*)d_in[7];
    const float* bk    = (const float*)d_in[8];
    const float* wv    = (const float*)d_in[9];
    const float* bv    = (const float*)d_in[10];
    const float* wo    = (const float*)d_in[11];
    const float* bo    = (const float*)d_in[12];
    const float* ln_g  = (const float*)d_in[13];
    const float* ln_b  = (const float*)d_in[14];
    float* out = (float*)d_out;

    const int gemm_smem = (2*AS_SZ + 2*BS_SZ) * (int)sizeof(float);        // 71,680 B
    const int attn_smem = (4*KV_SZ + 128*KV_STR) * (int)sizeof(float);     // 104,448 B
    cudaFuncSetAttribute((const void*)gemm_qkv_kernel,
                         cudaFuncAttributeMaxDynamicSharedMemorySize, gemm_smem);
    cudaFuncSetAttribute((const void*)gemm_out_kernel,
                         cudaFuncAttributeMaxDynamicSharedMemorySize, gemm_smem);
    cudaFuncSetAttribute((const void*)attn_kernel,
                         cudaFuncAttributeMaxDynamicSharedMemorySize, attn_smem);

    gemm_qkv_kernel<<<dim3(8, 16, 3), 256, gemm_smem>>>(q, k, v, wq, bq, wk, bk, wv, bv);
    attn_kernel<<<dim3(4, NH, NB), 256, attn_smem>>>(bias, gbias);
    gemm_out_kernel<<<dim3(8, 16), 256, gemm_smem>>>(q, wo, bo);
    ln_kernel<<<BL, 256>>>(ln_g, ln_b, out);
}